// round 8
// baseline (speedup 1.0000x reference)
#include <cuda_runtime.h>
#include <cuda_fp16.h>
#include <cstdint>
#include <math.h>

// ---------------------------------------------------------------- problem
namespace {
constexpr int B = 4, H = 16, S = 2048, Dh = 64;
constexpr int BM = 128;          // query rows per CTA (4 warps x 32 rows)
constexpr int BN = 64;           // keys per tile
constexpr int TILES = S / BN;    // 32
constexpr float QSCALE = 0.125f * 1.44269504089f;  // 1/sqrt(64) * log2(e) folded into Q
constexpr size_t NELEM = (size_t)B * H * S * Dh;

// smem layout (bytes): half tiles, 64 rows x 128B, XOR-swizzled
constexpr int KOFF0 = 0;
constexpr int KOFF1 = 8192;
constexpr int VOFF0 = 16384;
constexpr int VOFF1 = 24576;
constexpr int SMEM_BYTES = 32768;
}

__device__ unsigned g_mbits[(size_t)B * S * (S / 32)];
__device__ __half g_kh[NELEM];
__device__ __half g_vh[NELEM];

// ---------------------------------------------------------------- helpers
__device__ __forceinline__ uint32_t smem_u32(const void* p) {
    uint32_t a;
    asm("{ .reg .u64 t; cvta.to.shared.u64 t, %1; cvt.u32.u64 %0, t; }" : "=r"(a) : "l"(p));
    return a;
}
__device__ __forceinline__ uint32_t packf16(float lo, float hi) {
    uint32_t d;
    asm("cvt.rn.f16x2.f32 %0, %1, %2;" : "=r"(d) : "f"(hi), "f"(lo));
    return d;
}
__device__ __forceinline__ float ex2f(float x) {
    float y; asm("ex2.approx.f32 %0, %1;" : "=f"(y) : "f"(x)); return y;
}
__device__ __forceinline__ void mma_f16(float* c, const uint32_t* a, const uint32_t* b) {
    asm volatile(
        "mma.sync.aligned.m16n8k16.row.col.f32.f16.f16.f32 "
        "{%0,%1,%2,%3}, {%4,%5,%6,%7}, {%8,%9}, {%0,%1,%2,%3};"
        : "+f"(c[0]), "+f"(c[1]), "+f"(c[2]), "+f"(c[3])
        : "r"(a[0]), "r"(a[1]), "r"(a[2]), "r"(a[3]), "r"(b[0]), "r"(b[1]));
}
#define LDSM_X4(r0, r1, r2, r3, a)                                               \
    asm volatile("ldmatrix.sync.aligned.m8n8.x4.shared.b16 {%0,%1,%2,%3}, [%4];" \
                 : "=r"(r0), "=r"(r1), "=r"(r2), "=r"(r3) : "r"(a))
#define LDSM_X4_T(r0, r1, r2, r3, a)                                                   \
    asm volatile("ldmatrix.sync.aligned.m8n8.x4.trans.shared.b16 {%0,%1,%2,%3}, [%4];" \
                 : "=r"(r0), "=r"(r1), "=r"(r2), "=r"(r3) : "r"(a))
#define CP16(dst, src) \
    asm volatile("cp.async.cg.shared.global [%0], [%1], 16;" :: "r"(dst), "l"(src) : "memory")
#define CP_COMMIT() asm volatile("cp.async.commit_group;" ::: "memory")
#define CP_WAIT(n)  asm volatile("cp.async.wait_group %0;" :: "n"(n) : "memory")

__device__ __forceinline__ uint32_t sw_off(int row, int chunk) {
    return (uint32_t)(row * 128 + ((chunk ^ (row & 7)) << 4));
}

// ---------------------------------------------------------------- pre-pass
__global__ void pack_mask(const int* __restrict__ m) {
    const size_t i = (size_t)blockIdx.x * blockDim.x + threadIdx.x;
    const int4 t = reinterpret_cast<const int4*>(m)[i];
    unsigned nib = (unsigned)(t.x != 0) | ((unsigned)(t.y != 0) << 1) |
                   ((unsigned)(t.z != 0) << 2) | ((unsigned)(t.w != 0) << 3);
    unsigned v = nib << ((threadIdx.x & 7) * 4);
    v |= __shfl_xor_sync(0xffffffffu, v, 1);
    v |= __shfl_xor_sync(0xffffffffu, v, 2);
    v |= __shfl_xor_sync(0xffffffffu, v, 4);
    if ((threadIdx.x & 7) == 0) g_mbits[i >> 3] = v;
}
__global__ void cvt_half(const float* __restrict__ k, const float* __restrict__ v) {
    size_t i = ((size_t)blockIdx.x * blockDim.x + threadIdx.x) * 4;
    float4 tk = *reinterpret_cast<const float4*>(k + i);
    float4 tv = *reinterpret_cast<const float4*>(v + i);
    uint2 uk = make_uint2(packf16(tk.x, tk.y), packf16(tk.z, tk.w));
    uint2 uv = make_uint2(packf16(tv.x, tv.y), packf16(tv.z, tv.w));
    *reinterpret_cast<uint2*>(g_kh + i) = uk;
    *reinterpret_cast<uint2*>(g_vh + i) = uv;
}

// ---------------------------------------------------------------- attention
__global__ __launch_bounds__(128, 2) void attn_mma(
    const float* __restrict__ Q, float* __restrict__ Out)
{
    extern __shared__ char smc[];
    const uint32_t smb = smem_u32(smc);

    const int tid  = threadIdx.x;
    const int lane = tid & 31;
    const int wid  = tid >> 5;         // 0..3
    const int gid  = lane >> 2;
    const int twoq = (lane & 3) * 2;
    const int mat  = lane >> 3, mr = lane & 7;

    const int bh = blockIdx.y;
    const int b  = bh >> 4;            // H == 16
    const int qbase = blockIdx.x * BM;
    const int qrow  = qbase + wid * 32 + gid;   // rows: qrow, +8 (blk a); +16, +24 (blk b)

    const float*  qp = Q + (size_t)bh * S * Dh;
    const __half* kp = g_kh + (size_t)bh * S * Dh;
    const __half* vp = g_vh + (size_t)bh * S * Dh;

    // staging: 512 chunks/tensor, 128 threads -> 4 K + 4 V chunks each
    // ---- stage tile 0
    #pragma unroll
    for (int j = 0; j < 4; ++j) {
        const int c = j * 128 + tid, row = c >> 3, col = c & 7;
        CP16(smb + KOFF0 + sw_off(row, col), kp + row * Dh + col * 8);
        CP16(smb + VOFF0 + sw_off(row, col), vp + row * Dh + col * 8);
    }
    CP_COMMIT();

    // ---- Q fragments (pre-scaled by 1/8*log2e), two 16-row blocks
    uint32_t qa[4][4], qb[4][4];
    {
        const float* r0 = qp + (size_t)qrow * Dh;
        #pragma unroll
        for (int kt = 0; kt < 4; ++kt) {
            const int d0 = kt * 16 + twoq;
            #pragma unroll
            for (int h = 0; h < 2; ++h) {       // h=0 -> qa, h=1 -> qb
                const float* p0 = r0 + (h * 16) * Dh;
                const float* p8 = p0 + 8 * Dh;
                float2 x0 = *(const float2*)(p0 + d0);
                float2 x8 = *(const float2*)(p8 + d0);
                float2 y0 = *(const float2*)(p0 + d0 + 8);
                float2 y8 = *(const float2*)(p8 + d0 + 8);
                uint32_t* dst = h ? qb[kt] : qa[kt];
                dst[0] = packf16(x0.x * QSCALE, x0.y * QSCALE);
                dst[1] = packf16(x8.x * QSCALE, x8.y * QSCALE);
                dst[2] = packf16(y0.x * QSCALE, y0.y * QSCALE);
                dst[3] = packf16(y8.x * QSCALE, y8.y * QSCALE);
            }
        }
    }

    float ofa[8][4], ofb[8][4];
    #pragma unroll
    for (int nt = 0; nt < 8; ++nt)
        #pragma unroll
        for (int j = 0; j < 4; ++j) { ofa[nt][j] = 0.f; ofb[nt][j] = 0.f; }
    float la0 = 0.f, la1 = 0.f, lb0 = 0.f, lb1 = 0.f;

    const unsigned* mbase = g_mbits + ((size_t)(b * S) + qrow) * (S / 32);

    for (int t = 0; t < TILES; ++t) {
        // ---- prefetch tile t+1
        if (t + 1 < TILES) {
            const uint32_t ko = smb + (((t + 1) & 1) ? KOFF1 : KOFF0);
            const uint32_t vo = smb + (((t + 1) & 1) ? VOFF1 : VOFF0);
            const __half* ks = kp + (size_t)(t + 1) * BN * Dh;
            const __half* vs = vp + (size_t)(t + 1) * BN * Dh;
            #pragma unroll
            for (int j = 0; j < 4; ++j) {
                const int c = j * 128 + tid, row = c >> 3, col = c & 7;
                CP16(ko + sw_off(row, col), ks + row * Dh + col * 8);
                CP16(vo + sw_off(row, col), vs + row * Dh + col * 8);
            }
            CP_COMMIT();
            CP_WAIT(1);
        } else {
            CP_WAIT(0);
        }

        // mask words for the 4 row-blocks this thread touches
        const uint2 ma0 = *(const uint2*)(mbase + t * 2);
        const uint2 ma8 = *(const uint2*)(mbase +  8 * (S / 32) + t * 2);
        const uint2 mb0 = *(const uint2*)(mbase + 16 * (S / 32) + t * 2);
        const uint2 mb8 = *(const uint2*)(mbase + 24 * (S / 32) + t * 2);

        __syncthreads();
        const uint32_t Kb = smb + ((t & 1) ? KOFF1 : KOFF0);
        const uint32_t Vb = smb + ((t & 1) ? VOFF1 : VOFF0);

        // ---- MMA1 + fused mask/exp/pack, per 16-key group (interleaves MUFU with LDSM/HMMA)
        uint32_t paa[4][4], pab[4][4];
        #pragma unroll
        for (int ntp = 0; ntp < 4; ++ntp) {
            float sa0[4] = {0,0,0,0}, sa1[4] = {0,0,0,0};
            float sb0[4] = {0,0,0,0}, sb1[4] = {0,0,0,0};
            const int key = ntp * 16 + ((mat & 2) << 2) + mr;
            #pragma unroll
            for (int kt = 0; kt < 4; ++kt) {
                uint32_t b0, b1, b2, b3;
                LDSM_X4(b0, b1, b2, b3, Kb + sw_off(key, 2 * kt + (mat & 1)));
                uint32_t f0[2] = { b0, b1 }, f1[2] = { b2, b3 };
                mma_f16(sa0, qa[kt], f0); mma_f16(sa1, qa[kt], f1);
                mma_f16(sb0, qb[kt], f0); mma_f16(sb1, qb[kt], f1);
            }
            // mask bits: sh0 for nt=2ntp, sh1 for nt=2ntp+1; word .x for ntp<2
            const int sh0 = ((2 * ntp) & 3) * 8 + twoq;
            const int sh1 = sh0 + 8;
            const unsigned wa0 = (ntp < 2 ? ma0.x : ma0.y);
            const unsigned wa8 = (ntp < 2 ? ma8.x : ma8.y);
            const unsigned wb0 = (ntp < 2 ? mb0.x : mb0.y);
            const unsigned wb8 = (ntp < 2 ? mb8.x : mb8.y);

            float e;
            e = (wa0 >> sh0      & 1u) ? ex2f(sa0[0]) : 0.f; la0 += e; sa0[0] = e;
            e = (wa0 >> (sh0+1)  & 1u) ? ex2f(sa0[1]) : 0.f; la0 += e; sa0[1] = e;
            e = (wa8 >> sh0      & 1u) ? ex2f(sa0[2]) : 0.f; la1 += e; sa0[2] = e;
            e = (wa8 >> (sh0+1)  & 1u) ? ex2f(sa0[3]) : 0.f; la1 += e; sa0[3] = e;
            e = (wa0 >> sh1      & 1u) ? ex2f(sa1[0]) : 0.f; la0 += e; sa1[0] = e;
            e = (wa0 >> (sh1+1)  & 1u) ? ex2f(sa1[1]) : 0.f; la0 += e; sa1[1] = e;
            e = (wa8 >> sh1      & 1u) ? ex2f(sa1[2]) : 0.f; la1 += e; sa1[2] = e;
            e = (wa8 >> (sh1+1)  & 1u) ? ex2f(sa1[3]) : 0.f; la1 += e; sa1[3] = e;
            e = (wb0 >> sh0      & 1u) ? ex2f(sb0[0]) : 0.f; lb0 += e; sb0[0] = e;
            e = (wb0 >> (sh0+1)  & 1u) ? ex2f(sb0[1]) : 0.f; lb0 += e; sb0[1] = e;
            e = (wb8 >> sh0      & 1u) ? ex2f(sb0[2]) : 0.f; lb1 += e; sb0[2] = e;
            e = (wb8 >> (sh0+1)  & 1u) ? ex2f(sb0[3]) : 0.f; lb1 += e; sb0[3] = e;
            e = (wb0 >> sh1      & 1u) ? ex2f(sb1[0]) : 0.f; lb0 += e; sb1[0] = e;
            e = (wb0 >> (sh1+1)  & 1u) ? ex2f(sb1[1]) : 0.f; lb0 += e; sb1[1] = e;
            e = (wb8 >> sh1      & 1u) ? ex2f(sb1[2]) : 0.f; lb1 += e; sb1[2] = e;
            e = (wb8 >> (sh1+1)  & 1u) ? ex2f(sb1[3]) : 0.f; lb1 += e; sb1[3] = e;

            // P fragments (k-group = ntp)
            paa[ntp][0] = packf16(sa0[0], sa0[1]); paa[ntp][1] = packf16(sa0[2], sa0[3]);
            paa[ntp][2] = packf16(sa1[0], sa1[1]); paa[ntp][3] = packf16(sa1[2], sa1[3]);
            pab[ntp][0] = packf16(sb0[0], sb0[1]); pab[ntp][1] = packf16(sb0[2], sb0[3]);
            pab[ntp][2] = packf16(sb1[0], sb1[1]); pab[ntp][3] = packf16(sb1[2], sb1[3]);
        }

        // ---- MMA2: O += P V   (one LDSM feeds 4 MMAs)
        #pragma unroll
        for (int kt = 0; kt < 4; ++kt) {
            const int key = kt * 16 + ((mat & 1) << 3) + mr;
            #pragma unroll
            for (int ntp = 0; ntp < 4; ++ntp) {
                uint32_t b0, b1, b2, b3;
                LDSM_X4_T(b0, b1, b2, b3, Vb + sw_off(key, 2 * ntp + (mat >> 1)));
                uint32_t f0[2] = { b0, b1 }, f1[2] = { b2, b3 };
                mma_f16(ofa[2 * ntp],     paa[kt], f0);
                mma_f16(ofa[2 * ntp + 1], paa[kt], f1);
                mma_f16(ofb[2 * ntp],     pab[kt], f0);
                mma_f16(ofb[2 * ntp + 1], pab[kt], f1);
            }
        }
        __syncthreads();
    }

    // ---- epilogue
    la0 += __shfl_xor_sync(0xffffffffu, la0, 1); la0 += __shfl_xor_sync(0xffffffffu, la0, 2);
    la1 += __shfl_xor_sync(0xffffffffu, la1, 1); la1 += __shfl_xor_sync(0xffffffffu, la1, 2);
    lb0 += __shfl_xor_sync(0xffffffffu, lb0, 1); lb0 += __shfl_xor_sync(0xffffffffu, lb0, 2);
    lb1 += __shfl_xor_sync(0xffffffffu, lb1, 1); lb1 += __shfl_xor_sync(0xffffffffu, lb1, 2);
    const float ia0 = 1.f / la0, ia1 = 1.f / la1, ib0 = 1.f / lb0, ib1 = 1.f / lb1;

    float* o0 = Out + ((size_t)bh * S + qrow) * Dh;
    #pragma unroll
    for (int nt = 0; nt < 8; ++nt) {
        const int d = nt * 8 + twoq;
        *(float2*)(o0 +            d) = make_float2(ofa[nt][0] * ia0, ofa[nt][1] * ia0);
        *(float2*)(o0 +  8 * Dh + d) = make_float2(ofa[nt][2] * ia1, ofa[nt][3] * ia1);
        *(float2*)(o0 + 16 * Dh + d) = make_float2(ofb[nt][0] * ib0, ofb[nt][1] * ib0);
        *(float2*)(o0 + 24 * Dh + d) = make_float2(ofb[nt][2] * ib1, ofb[nt][3] * ib1);
    }
}

// ---------------------------------------------------------------- launch
extern "C" void kernel_launch(void* const* d_in, const int* in_sizes, int n_in,
                              void* d_out, int out_size)
{
    const float* q    = (const float*)d_in[0];
    const float* k    = (const float*)d_in[1];
    const float* v    = (const float*)d_in[2];
    const int*   mask = (const int*)d_in[3];
    float* out = (float*)d_out;

    pack_mask<<<(B * S * S) / 4 / 256, 256>>>(mask);
    cvt_half<<<(int)(NELEM / 4 / 256), 256>>>(k, v);

    cudaFuncSetAttribute(attn_mma, cudaFuncAttributeMaxDynamicSharedMemorySize, SMEM_BYTES);
    dim3 grid(S / BM, B * H);   // 16 x 64 = 1024 CTAs
    attn_mma<<<grid, 128, SMEM_BYTES>>>(q, out);
}

// round 9
// speedup vs baseline: 1.0825x; 1.0825x over previous
#include <cuda_runtime.h>
#include <cuda_fp16.h>
#include <cstdint>
#include <math.h>

// ---------------------------------------------------------------- problem
namespace {
constexpr int B = 4, H = 16, S = 2048, Dh = 64;
constexpr int BM = 128;          // query rows per CTA (8 warps x 16 rows)
constexpr int BN = 64;           // keys per tile
constexpr int TILES = S / BN;    // 32
constexpr float QSCALE = 0.125f * 1.44269504089f;  // 1/sqrt(64) * log2(e) folded into Q
constexpr size_t NELEM = (size_t)B * H * S * Dh;   // 8.39M

// smem layout (bytes): half tiles, 64 rows x 128B (64 halves), XOR-swizzled
constexpr int KOFF0 = 0;
constexpr int KOFF1 = 8192;
constexpr int VOFF0 = 16384;
constexpr int VOFF1 = 24576;
constexpr int SMEM_BYTES = 32768;
}

// scratch: bit-packed mask + fp16 K/V
__device__ unsigned g_mbits[(size_t)B * S * (S / 32)];
__device__ __half g_kh[NELEM];
__device__ __half g_vh[NELEM];

// ---------------------------------------------------------------- helpers
__device__ __forceinline__ uint32_t smem_u32(const void* p) {
    uint32_t a;
    asm("{ .reg .u64 t; cvta.to.shared.u64 t, %1; cvt.u32.u64 %0, t; }" : "=r"(a) : "l"(p));
    return a;
}
__device__ __forceinline__ uint32_t packf16(float lo, float hi) {
    uint32_t d;
    asm("cvt.rn.f16x2.f32 %0, %1, %2;" : "=r"(d) : "f"(hi), "f"(lo));
    return d;
}
__device__ __forceinline__ float ex2f(float x) {
    float y; asm("ex2.approx.f32 %0, %1;" : "=f"(y) : "f"(x)); return y;
}
__device__ __forceinline__ void mma_f16(float* c, const uint32_t* a, const uint32_t* b) {
    asm volatile(
        "mma.sync.aligned.m16n8k16.row.col.f32.f16.f16.f32 "
        "{%0,%1,%2,%3}, {%4,%5,%6,%7}, {%8,%9}, {%0,%1,%2,%3};"
        : "+f"(c[0]), "+f"(c[1]), "+f"(c[2]), "+f"(c[3])
        : "r"(a[0]), "r"(a[1]), "r"(a[2]), "r"(a[3]), "r"(b[0]), "r"(b[1]));
}
#define LDSM_X4(r0, r1, r2, r3, a)                                               \
    asm volatile("ldmatrix.sync.aligned.m8n8.x4.shared.b16 {%0,%1,%2,%3}, [%4];" \
                 : "=r"(r0), "=r"(r1), "=r"(r2), "=r"(r3) : "r"(a))
#define LDSM_X4_T(r0, r1, r2, r3, a)                                                   \
    asm volatile("ldmatrix.sync.aligned.m8n8.x4.trans.shared.b16 {%0,%1,%2,%3}, [%4];" \
                 : "=r"(r0), "=r"(r1), "=r"(r2), "=r"(r3) : "r"(a))
#define CP16(dst, src) \
    asm volatile("cp.async.cg.shared.global [%0], [%1], 16;" :: "r"(dst), "l"(src) : "memory")
#define CP_COMMIT() asm volatile("cp.async.commit_group;" ::: "memory")
#define CP_WAIT(n)  asm volatile("cp.async.wait_group %0;" :: "n"(n) : "memory")

// swizzled byte offset within a tile: row (key) 0..63, chunk (16B) 0..7
__device__ __forceinline__ uint32_t sw_off(int row, int chunk) {
    return (uint32_t)(row * 128 + ((chunk ^ (row & 7)) << 4));
}

// ---------------------------------------------------------------- pre-pass
__global__ void pack_mask(const int* __restrict__ m) {
    const size_t i = (size_t)blockIdx.x * blockDim.x + threadIdx.x;
    const int4 t = reinterpret_cast<const int4*>(m)[i];
    unsigned nib = (unsigned)(t.x != 0) | ((unsigned)(t.y != 0) << 1) |
                   ((unsigned)(t.z != 0) << 2) | ((unsigned)(t.w != 0) << 3);
    unsigned v = nib << ((threadIdx.x & 7) * 4);
    v |= __shfl_xor_sync(0xffffffffu, v, 1);
    v |= __shfl_xor_sync(0xffffffffu, v, 2);
    v |= __shfl_xor_sync(0xffffffffu, v, 4);
    if ((threadIdx.x & 7) == 0) g_mbits[i >> 3] = v;
}
__global__ void cvt_half(const float* __restrict__ k, const float* __restrict__ v) {
    size_t i = ((size_t)blockIdx.x * blockDim.x + threadIdx.x) * 4;
    float4 tk = *reinterpret_cast<const float4*>(k + i);
    float4 tv = *reinterpret_cast<const float4*>(v + i);
    uint2 uk = make_uint2(packf16(tk.x, tk.y), packf16(tk.z, tk.w));
    uint2 uv = make_uint2(packf16(tv.x, tv.y), packf16(tv.z, tv.w));
    *reinterpret_cast<uint2*>(g_kh + i) = uk;
    *reinterpret_cast<uint2*>(g_vh + i) = uv;
}

// ---------------------------------------------------------------- attention
__global__ __launch_bounds__(256, 2) void attn_mma(
    const float* __restrict__ Q, float* __restrict__ Out)
{
    extern __shared__ char smc[];
    const uint32_t smb = smem_u32(smc);

    const int tid  = threadIdx.x;
    const int lane = tid & 31;
    const int wid  = tid >> 5;
    const int gid  = lane >> 2;        // 0..7
    const int twoq = (lane & 3) * 2;   // 0,2,4,6

    const int bh = blockIdx.y;
    const int b  = bh >> 4;            // H == 16
    const int qbase = blockIdx.x * BM;
    const int qrow  = qbase + wid * 16 + gid;   // row0; row1 = qrow + 8

    const float*  qp = Q + (size_t)bh * S * Dh;
    const __half* kp = g_kh + (size_t)bh * S * Dh;
    const __half* vp = g_vh + (size_t)bh * S * Dh;

    // staging: 512 16B-chunks per tensor per tile; 2 per thread
    const int c0r = tid >> 3,         c0c = tid & 7;
    const int c1r = (tid + 256) >> 3, c1c = tid & 7;

    // ---- stage tile 0
    CP16(smb + KOFF0 + sw_off(c0r, c0c), kp + c0r * Dh + c0c * 8);
    CP16(smb + KOFF0 + sw_off(c1r, c1c), kp + c1r * Dh + c1c * 8);
    CP16(smb + VOFF0 + sw_off(c0r, c0c), vp + c0r * Dh + c0c * 8);
    CP16(smb + VOFF0 + sw_off(c1r, c1c), vp + c1r * Dh + c1c * 8);
    CP_COMMIT();

    // ---- Q fragments (pre-scaled by 1/8*log2e), reused for all tiles
    uint32_t qa[4][4];
    {
        const float* q0 = qp + (size_t)qrow * Dh;
        const float* q8 = q0 + 8 * Dh;
        #pragma unroll
        for (int kt = 0; kt < 4; ++kt) {
            const int d0 = kt * 16 + twoq;
            float2 x0 = *(const float2*)(q0 + d0);
            float2 x8 = *(const float2*)(q8 + d0);
            float2 y0 = *(const float2*)(q0 + d0 + 8);
            float2 y8 = *(const float2*)(q8 + d0 + 8);
            qa[kt][0] = packf16(x0.x * QSCALE, x0.y * QSCALE);
            qa[kt][1] = packf16(x8.x * QSCALE, x8.y * QSCALE);
            qa[kt][2] = packf16(y0.x * QSCALE, y0.y * QSCALE);
            qa[kt][3] = packf16(y8.x * QSCALE, y8.y * QSCALE);
        }
    }

    float of[8][4];
    #pragma unroll
    for (int nt = 0; nt < 8; ++nt)
        #pragma unroll
        for (int j = 0; j < 4; ++j) of[nt][j] = 0.f;
    float l0 = 0.f, l1 = 0.f;

    const unsigned* mrow = g_mbits + ((size_t)(b * S) + qrow) * (S / 32);

    for (int t = 0; t < TILES; ++t) {
        // ---- prefetch tile t+1
        if (t + 1 < TILES) {
            const uint32_t ko = smb + (((t + 1) & 1) ? KOFF1 : KOFF0);
            const uint32_t vo = smb + (((t + 1) & 1) ? VOFF1 : VOFF0);
            const __half* ks = kp + (size_t)(t + 1) * BN * Dh;
            const __half* vs = vp + (size_t)(t + 1) * BN * Dh;
            CP16(ko + sw_off(c0r, c0c), ks + c0r * Dh + c0c * 8);
            CP16(ko + sw_off(c1r, c1c), ks + c1r * Dh + c1c * 8);
            CP16(vo + sw_off(c0r, c0c), vs + c0r * Dh + c0c * 8);
            CP16(vo + sw_off(c1r, c1c), vs + c1r * Dh + c1c * 8);
            CP_COMMIT();
            CP_WAIT(1);
        } else {
            CP_WAIT(0);
        }

        uint2 mwa = *(const uint2*)(mrow + t * 2);
        uint2 mwb = *(const uint2*)(mrow + 8 * (S / 32) + t * 2);

        __syncthreads();
        const uint32_t Kb = smb + ((t & 1) ? KOFF1 : KOFF0);
        const uint32_t Vb = smb + ((t & 1) ? VOFF1 : VOFF0);

        // ---- MMA1: S2 = (Q*scale*log2e) K^T ; B frags via ldmatrix (non-trans)
        float sf[8][4];
        #pragma unroll
        for (int nt = 0; nt < 8; ++nt)
            #pragma unroll
            for (int j = 0; j < 4; ++j) sf[nt][j] = 0.f;

        const int mat = lane >> 3, mr = lane & 7;
        #pragma unroll
        for (int kt = 0; kt < 4; ++kt) {
            #pragma unroll
            for (int ntp = 0; ntp < 4; ++ntp) {
                const int key   = ntp * 16 + ((mat & 2) << 2) + mr;
                const int chunk = 2 * kt + (mat & 1);
                uint32_t b0, b1, b2, b3;
                LDSM_X4(b0, b1, b2, b3, Kb + sw_off(key, chunk));
                uint32_t f0[2] = { b0, b1 }, f1[2] = { b2, b3 };
                mma_f16(sf[2 * ntp],     qa[kt], f0);
                mma_f16(sf[2 * ntp + 1], qa[kt], f1);
            }
        }

        // ---- mask + 2^s (unnormalized softmax in base-2)
        #pragma unroll
        for (int nt = 0; nt < 8; ++nt) {
            const int sh = (nt & 3) * 8 + twoq;
            const unsigned wa = ((nt < 4) ? mwa.x : mwa.y) >> sh;
            const unsigned wb = ((nt < 4) ? mwb.x : mwb.y) >> sh;
            float e0 = (wa & 1u) ? ex2f(sf[nt][0]) : 0.f;
            float e1 = (wa & 2u) ? ex2f(sf[nt][1]) : 0.f;
            float e2 = (wb & 1u) ? ex2f(sf[nt][2]) : 0.f;
            float e3 = (wb & 2u) ? ex2f(sf[nt][3]) : 0.f;
            l0 += e0 + e1; l1 += e2 + e3;
            sf[nt][0] = e0; sf[nt][1] = e1; sf[nt][2] = e2; sf[nt][3] = e3;
        }

        // ---- P fragments: C layout maps onto A layout (pure cvt)
        uint32_t pa[4][4];
        #pragma unroll
        for (int kt = 0; kt < 4; ++kt) {
            pa[kt][0] = packf16(sf[2 * kt][0],     sf[2 * kt][1]);
            pa[kt][1] = packf16(sf[2 * kt][2],     sf[2 * kt][3]);
            pa[kt][2] = packf16(sf[2 * kt + 1][0], sf[2 * kt + 1][1]);
            pa[kt][3] = packf16(sf[2 * kt + 1][2], sf[2 * kt + 1][3]);
        }

        // ---- MMA2: O += P V ; B frags via ldmatrix.trans
        #pragma unroll
        for (int kt = 0; kt < 4; ++kt) {
            #pragma unroll
            for (int ntp = 0; ntp < 4; ++ntp) {
                const int key   = kt * 16 + ((mat & 1) << 3) + mr;
                const int chunk = 2 * ntp + (mat >> 1);
                uint32_t b0, b1, b2, b3;
                LDSM_X4_T(b0, b1, b2, b3, Vb + sw_off(key, chunk));
                uint32_t f0[2] = { b0, b1 }, f1[2] = { b2, b3 };
                mma_f16(of[2 * ntp],     pa[kt], f0);
                mma_f16(of[2 * ntp + 1], pa[kt], f1);
            }
        }
        __syncthreads();   // buffer reads done before re-staging
    }

    // ---- epilogue: normalize and store
    l0 += __shfl_xor_sync(0xffffffffu, l0, 1);
    l0 += __shfl_xor_sync(0xffffffffu, l0, 2);
    l1 += __shfl_xor_sync(0xffffffffu, l1, 1);
    l1 += __shfl_xor_sync(0xffffffffu, l1, 2);
    const float inv0 = 1.0f / l0, inv1 = 1.0f / l1;

    float* o0 = Out + ((size_t)bh * S + qrow) * Dh;
    float* o8 = o0 + 8 * Dh;
    #pragma unroll
    for (int nt = 0; nt < 8; ++nt) {
        const int d = nt * 8 + twoq;
        *(float2*)(o0 + d) = make_float2(of[nt][0] * inv0, of[nt][1] * inv0);
        *(float2*)(o8 + d) = make_float2(of[nt][2] * inv1, of[nt][3] * inv1);
    }
}

// ---------------------------------------------------------------- launch
extern "C" void kernel_launch(void* const* d_in, const int* in_sizes, int n_in,
                              void* d_out, int out_size)
{
    const float* q    = (const float*)d_in[0];
    const float* k    = (const float*)d_in[1];
    const float* v    = (const float*)d_in[2];
    const int*   mask = (const int*)d_in[3];
    float* out = (float*)d_out;

    pack_mask<<<(B * S * S) / 4 / 256, 256>>>(mask);
    cvt_half<<<(int)(NELEM / 4 / 256), 256>>>(k, v);

    cudaFuncSetAttribute(attn_mma, cudaFuncAttributeMaxDynamicSharedMemorySize, SMEM_BYTES);
    dim3 grid(S / BM, B * H);   // 16 x 64 = 1024 CTAs
    attn_mma<<<grid, 256, SMEM_BYTES>>>(q, out);
}

// round 11
// speedup vs baseline: 1.1483x; 1.0608x over previous
#include <cuda_runtime.h>
#include <cuda_fp16.h>
#include <cstdint>
#include <math.h>

// ---------------------------------------------------------------- problem
namespace {
constexpr int B = 4, H = 16, S = 2048, Dh = 64;
constexpr int BM = 128;          // query rows per CTA (8 warps x 16 rows)
constexpr int BN = 64;           // keys per tile
constexpr int TILES = S / BN;    // 32
constexpr float QSCALE = 0.125f * 1.44269504089f;  // 1/sqrt(64) * log2(e) folded into Q
constexpr size_t NELEM = (size_t)B * H * S * Dh;   // 8.39M

// smem (bytes): half tiles 64 rows x 128B, XOR-swizzled, TRIPLE buffered
// K buffers at bi*8192 (bi=0..2), V buffers at 24576 + bi*8192
constexpr int TILE_BYTES = 8192;
constexpr int VBASE = 3 * TILE_BYTES;      // 24576
constexpr int SMEM_BYTES = 6 * TILE_BYTES; // 49152

constexpr int MASK_BLOCKS = (B * S * S / 4) / 256;   // 16384
constexpr int CVT_BLOCKS  = (int)(NELEM / 4 / 256);  // 8192
}

// scratch: bit-packed mask + fp16 K/V
__device__ unsigned g_mbits[(size_t)B * S * (S / 32)];
__device__ __half g_kh[NELEM];
__device__ __half g_vh[NELEM];

// ---------------------------------------------------------------- helpers
__device__ __forceinline__ uint32_t smem_u32(const void* p) {
    uint32_t a;
    asm("{ .reg .u64 t; cvta.to.shared.u64 t, %1; cvt.u32.u64 %0, t; }" : "=r"(a) : "l"(p));
    return a;
}
__device__ __forceinline__ uint32_t packf16(float lo, float hi) {
    uint32_t d;
    asm("cvt.rn.f16x2.f32 %0, %1, %2;" : "=r"(d) : "f"(hi), "f"(lo));
    return d;
}
__device__ __forceinline__ float ex2f(float x) {
    float y; asm("ex2.approx.f32 %0, %1;" : "=f"(y) : "f"(x)); return y;
}
__device__ __forceinline__ void mma_f16(float* c, const uint32_t* a, const uint32_t* b) {
    asm volatile(
        "mma.sync.aligned.m16n8k16.row.col.f32.f16.f16.f32 "
        "{%0,%1,%2,%3}, {%4,%5,%6,%7}, {%8,%9}, {%0,%1,%2,%3};"
        : "+f"(c[0]), "+f"(c[1]), "+f"(c[2]), "+f"(c[3])
        : "r"(a[0]), "r"(a[1]), "r"(a[2]), "r"(a[3]), "r"(b[0]), "r"(b[1]));
}
#define LDSM_X4(r0, r1, r2, r3, a)                                               \
    asm volatile("ldmatrix.sync.aligned.m8n8.x4.shared.b16 {%0,%1,%2,%3}, [%4];" \
                 : "=r"(r0), "=r"(r1), "=r"(r2), "=r"(r3) : "r"(a))
#define LDSM_X4_T(r0, r1, r2, r3, a)                                                   \
    asm volatile("ldmatrix.sync.aligned.m8n8.x4.trans.shared.b16 {%0,%1,%2,%3}, [%4];" \
                 : "=r"(r0), "=r"(r1), "=r"(r2), "=r"(r3) : "r"(a))
#define CP16(dst, src) \
    asm volatile("cp.async.cg.shared.global [%0], [%1], 16;" :: "r"(dst), "l"(src) : "memory")
#define CP_COMMIT() asm volatile("cp.async.commit_group;" ::: "memory")
#define CP_WAIT(n)  asm volatile("cp.async.wait_group %0;" :: "n"(n) : "memory")

// swizzled byte offset within a tile: row (key) 0..63, chunk (16B) 0..7
__device__ __forceinline__ uint32_t sw_off(int row, int chunk) {
    return (uint32_t)(row * 128 + ((chunk ^ (row & 7)) << 4));
}

// ---------------------------------------------------------------- fused pre-pass
// blocks [0, MASK_BLOCKS): bit-pack mask.  blocks [MASK_BLOCKS, +CVT_BLOCKS): K/V -> fp16.
__global__ void prepass(const float* __restrict__ k, const float* __restrict__ v,
                        const int* __restrict__ m) {
    if (blockIdx.x < MASK_BLOCKS) {
        const size_t i = (size_t)blockIdx.x * 256 + threadIdx.x;
        const int4 t = reinterpret_cast<const int4*>(m)[i];
        unsigned nib = (unsigned)(t.x != 0) | ((unsigned)(t.y != 0) << 1) |
                       ((unsigned)(t.z != 0) << 2) | ((unsigned)(t.w != 0) << 3);
        unsigned w = nib << ((threadIdx.x & 7) * 4);
        w |= __shfl_xor_sync(0xffffffffu, w, 1);
        w |= __shfl_xor_sync(0xffffffffu, w, 2);
        w |= __shfl_xor_sync(0xffffffffu, w, 4);
        if ((threadIdx.x & 7) == 0) g_mbits[i >> 3] = w;
    } else {
        const size_t i = ((size_t)(blockIdx.x - MASK_BLOCKS) * 256 + threadIdx.x) * 4;
        float4 tk = *reinterpret_cast<const float4*>(k + i);
        float4 tv = *reinterpret_cast<const float4*>(v + i);
        uint2 uk = make_uint2(packf16(tk.x, tk.y), packf16(tk.z, tk.w));
        uint2 uv = make_uint2(packf16(tv.x, tv.y), packf16(tv.z, tv.w));
        *reinterpret_cast<uint2*>(g_kh + i) = uk;
        *reinterpret_cast<uint2*>(g_vh + i) = uv;
    }
}

// ---------------------------------------------------------------- attention
__global__ __launch_bounds__(256, 2) void attn_mma(
    const float* __restrict__ Q, float* __restrict__ Out)
{
    extern __shared__ char smc[];
    const uint32_t smb = smem_u32(smc);

    const int tid  = threadIdx.x;
    const int lane = tid & 31;
    const int wid  = tid >> 5;
    const int gid  = lane >> 2;        // 0..7
    const int twoq = (lane & 3) * 2;   // 0,2,4,6
    const int mat  = lane >> 3, mr = lane & 7;

    const int bh = blockIdx.y;
    const int b  = bh >> 4;            // H == 16
    const int qbase = blockIdx.x * BM;
    const int qrow  = qbase + wid * 16 + gid;   // row0; row1 = qrow + 8

    const float*  qp = Q + (size_t)bh * S * Dh;
    const __half* kp = g_kh + (size_t)bh * S * Dh;
    const __half* vp = g_vh + (size_t)bh * S * Dh;

    // staging: 512 16B-chunks per tensor per tile; 2 per thread
    const int c0r = tid >> 3,         c0c = tid & 7;
    const int c1r = (tid + 256) >> 3, c1c = tid & 7;

    // ---- prologue: stage tiles 0 and 1
    #pragma unroll
    for (int pt = 0; pt < 2; ++pt) {
        const uint32_t ko = smb + pt * TILE_BYTES;
        const uint32_t vo = smb + VBASE + pt * TILE_BYTES;
        const __half* ks = kp + (size_t)pt * BN * Dh;
        const __half* vs = vp + (size_t)pt * BN * Dh;
        CP16(ko + sw_off(c0r, c0c), ks + c0r * Dh + c0c * 8);
        CP16(ko + sw_off(c1r, c1c), ks + c1r * Dh + c1c * 8);
        CP16(vo + sw_off(c0r, c0c), vs + c0r * Dh + c0c * 8);
        CP16(vo + sw_off(c1r, c1c), vs + c1r * Dh + c1c * 8);
        CP_COMMIT();
    }

    // ---- Q fragments (pre-scaled by 1/8*log2e), reused for all tiles
    uint32_t qa[4][4];
    {
        const float* q0 = qp + (size_t)qrow * Dh;
        const float* q8 = q0 + 8 * Dh;
        #pragma unroll
        for (int kt = 0; kt < 4; ++kt) {
            const int d0 = kt * 16 + twoq;
            float2 x0 = *(const float2*)(q0 + d0);
            float2 x8 = *(const float2*)(q8 + d0);
            float2 y0 = *(const float2*)(q0 + d0 + 8);
            float2 y8 = *(const float2*)(q8 + d0 + 8);
            qa[kt][0] = packf16(x0.x * QSCALE, x0.y * QSCALE);
            qa[kt][1] = packf16(x8.x * QSCALE, x8.y * QSCALE);
            qa[kt][2] = packf16(y0.x * QSCALE, y0.y * QSCALE);
            qa[kt][3] = packf16(y8.x * QSCALE, y8.y * QSCALE);
        }
    }

    float of[8][4];
    #pragma unroll
    for (int nt = 0; nt < 8; ++nt)
        #pragma unroll
        for (int j = 0; j < 4; ++j) of[nt][j] = 0.f;
    float l0 = 0.f, l1 = 0.f;

    const unsigned* mrow = g_mbits + ((size_t)(b * S) + qrow) * (S / 32);

    int bi = 0;    // buffer of tile t
    int si = 2;    // buffer of tile t+2 (staging target)
    for (int t = 0; t < TILES; ++t) {
        // ---- ensure tile t data arrived, fetch mask words (independent loads)
        if (t + 1 < TILES) { CP_WAIT(1); } else { CP_WAIT(0); }
        uint2 mwa = *(const uint2*)(mrow + t * 2);
        uint2 mwb = *(const uint2*)(mrow + 8 * (S / 32) + t * 2);

        __syncthreads();   // tile t visible to all; buffer si fully drained (read at t-1)

        // ---- stage tile t+2 into buffer si (freed by the barrier above)
        if (t + 2 < TILES) {
            const uint32_t ko = smb + si * TILE_BYTES;
            const uint32_t vo = smb + VBASE + si * TILE_BYTES;
            const __half* ks = kp + (size_t)(t + 2) * BN * Dh;
            const __half* vs = vp + (size_t)(t + 2) * BN * Dh;
            CP16(ko + sw_off(c0r, c0c), ks + c0r * Dh + c0c * 8);
            CP16(ko + sw_off(c1r, c1c), ks + c1r * Dh + c1c * 8);
            CP16(vo + sw_off(c0r, c0c), vs + c0r * Dh + c0c * 8);
            CP16(vo + sw_off(c1r, c1c), vs + c1r * Dh + c1c * 8);
            CP_COMMIT();
        }

        const uint32_t Kb = smb + bi * TILE_BYTES;
        const uint32_t Vb = smb + VBASE + bi * TILE_BYTES;

        // ---- MMA1: S2 = (Q*scale*log2e) K^T ; B frags via ldmatrix (non-trans)
        float sf[8][4];
        #pragma unroll
        for (int nt = 0; nt < 8; ++nt)
            #pragma unroll
            for (int j = 0; j < 4; ++j) sf[nt][j] = 0.f;

        #pragma unroll
        for (int kt = 0; kt < 4; ++kt) {
            #pragma unroll
            for (int ntp = 0; ntp < 4; ++ntp) {
                const int key   = ntp * 16 + ((mat & 2) << 2) + mr;
                const int chunk = 2 * kt + (mat & 1);
                uint32_t b0, b1, b2, b3;
                LDSM_X4(b0, b1, b2, b3, Kb + sw_off(key, chunk));
                uint32_t f0[2] = { b0, b1 }, f1[2] = { b2, b3 };
                mma_f16(sf[2 * ntp],     qa[kt], f0);
                mma_f16(sf[2 * ntp + 1], qa[kt], f1);
            }
        }

        // ---- mask + 2^s (unnormalized softmax in base-2)
        #pragma unroll
        for (int nt = 0; nt < 8; ++nt) {
            const int sh = (nt & 3) * 8 + twoq;
            const unsigned wa = ((nt < 4) ? mwa.x : mwa.y) >> sh;
            const unsigned wb = ((nt < 4) ? mwb.x : mwb.y) >> sh;
            float e0 = (wa & 1u) ? ex2f(sf[nt][0]) : 0.f;
            float e1 = (wa & 2u) ? ex2f(sf[nt][1]) : 0.f;
            float e2 = (wb & 1u) ? ex2f(sf[nt][2]) : 0.f;
            float e3 = (wb & 2u) ? ex2f(sf[nt][3]) : 0.f;
            l0 += e0 + e1; l1 += e2 + e3;
            sf[nt][0] = e0; sf[nt][1] = e1; sf[nt][2] = e2; sf[nt][3] = e3;
        }

        // ---- P fragments: C layout maps onto A layout (pure cvt)
        uint32_t pa[4][4];
        #pragma unroll
        for (int kt = 0; kt < 4; ++kt) {
            pa[kt][0] = packf16(sf[2 * kt][0],     sf[2 * kt][1]);
            pa[kt][1] = packf16(sf[2 * kt][2],     sf[2 * kt][3]);
            pa[kt][2] = packf16(sf[2 * kt + 1][0], sf[2 * kt + 1][1]);
            pa[kt][3] = packf16(sf[2 * kt + 1][2], sf[2 * kt + 1][3]);
        }

        // ---- MMA2: O += P V ; B frags via ldmatrix.trans
        #pragma unroll
        for (int kt = 0; kt < 4; ++kt) {
            #pragma unroll
            for (int ntp = 0; ntp < 4; ++ntp) {
                const int key   = kt * 16 + ((mat & 1) << 3) + mr;
                const int chunk = 2 * ntp + (mat >> 1);
                uint32_t b0, b1, b2, b3;
                LDSM_X4_T(b0, b1, b2, b3, Vb + sw_off(key, chunk));
                uint32_t f0[2] = { b0, b1 }, f1[2] = { b2, b3 };
                mma_f16(of[2 * ntp],     pa[kt], f0);
                mma_f16(of[2 * ntp + 1], pa[kt], f1);
            }
        }

        bi = (bi == 2) ? 0 : bi + 1;
        si = (si == 2) ? 0 : si + 1;
    }

    // ---- epilogue: normalize and store
    l0 += __shfl_xor_sync(0xffffffffu, l0, 1);
    l0 += __shfl_xor_sync(0xffffffffu, l0, 2);
    l1 += __shfl_xor_sync(0xffffffffu, l1, 1);
    l1 += __shfl_xor_sync(0xffffffffu, l1, 2);
    const float inv0 = 1.0f / l0, inv1 = 1.0f / l1;

    float* o0 = Out + ((size_t)bh * S + qrow) * Dh;
    float* o8 = o0 + 8 * Dh;
    #pragma unroll
    for (int nt = 0; nt < 8; ++nt) {
        const int d = nt * 8 + twoq;
        *(float2*)(o0 + d) = make_float2(of[nt][0] * inv0, of[nt][1] * inv0);
        *(float2*)(o8 + d) = make_float2(of[nt][2] * inv1, of[nt][3] * inv1);
    }
}

// ---------------------------------------------------------------- launch
extern "C" void kernel_launch(void* const* d_in, const int* in_sizes, int n_in,
                              void* d_out, int out_size)
{
    const float* q    = (const float*)d_in[0];
    const float* k    = (const float*)d_in[1];
    const float* v    = (const float*)d_in[2];
    const int*   mask = (const int*)d_in[3];
    float* out = (float*)d_out;

    prepass<<<MASK_BLOCKS + CVT_BLOCKS, 256>>>(k, v, mask);

    cudaFuncSetAttribute(attn_mma, cudaFuncAttributeMaxDynamicSharedMemorySize, SMEM_BYTES);
    dim3 grid(S / BM, B * H);   // 16 x 64 = 1024 CTAs
    attn_mma<<<grid, 256, SMEM_BYTES>>>(q, out);
}

// round 13
// speedup vs baseline: 1.2017x; 1.0465x over previous
#include <cuda_runtime.h>
#include <cuda_fp16.h>
#include <cstdint>
#include <math.h>

// ---------------------------------------------------------------- problem
namespace {
constexpr int B = 4, H = 16, S = 2048, Dh = 64;
constexpr int BM = 128;          // query rows per CTA (8 warps x 16 rows)
constexpr int BN = 64;           // keys per tile
constexpr int TILES = S / BN;    // 32
constexpr float QSCALE = 0.125f * 1.44269504089f;  // 1/sqrt(64) * log2(e) folded into Q
constexpr size_t NELEM = (size_t)B * H * S * Dh;   // 8.39M

// smem (bytes): half tiles 64 rows x 128B, XOR-swizzled, TRIPLE buffered
constexpr int TILE_BYTES = 8192;
constexpr int VBASE = 3 * TILE_BYTES;      // 24576
constexpr int SMEM_BYTES = 6 * TILE_BYTES; // 49152

constexpr int MASK_BLOCKS = (B * S * S / 4) / 256;   // 16384
constexpr int CVT_BLOCKS  = (int)(NELEM / 4 / 256);  // 8192
}

// scratch: bit-packed mask + fp16 K/V
__device__ unsigned g_mbits[(size_t)B * S * (S / 32)];
__device__ __half g_kh[NELEM];
__device__ __half g_vh[NELEM];

// ---------------------------------------------------------------- helpers
__device__ __forceinline__ uint32_t smem_u32(const void* p) {
    uint32_t a;
    asm("{ .reg .u64 t; cvta.to.shared.u64 t, %1; cvt.u32.u64 %0, t; }" : "=r"(a) : "l"(p));
    return a;
}
__device__ __forceinline__ uint32_t packf16(float lo, float hi) {
    uint32_t d;
    asm("cvt.rn.f16x2.f32 %0, %1, %2;" : "=r"(d) : "f"(hi), "f"(lo));
    return d;
}
__device__ __forceinline__ float ex2f(float x) {
    float y; asm("ex2.approx.f32 %0, %1;" : "=f"(y) : "f"(x)); return y;
}
__device__ __forceinline__ void mma_f16(float* c, const uint32_t* a, const uint32_t* b) {
    asm volatile(
        "mma.sync.aligned.m16n8k16.row.col.f32.f16.f16.f32 "
        "{%0,%1,%2,%3}, {%4,%5,%6,%7}, {%8,%9}, {%0,%1,%2,%3};"
        : "+f"(c[0]), "+f"(c[1]), "+f"(c[2]), "+f"(c[3])
        : "r"(a[0]), "r"(a[1]), "r"(a[2]), "r"(a[3]), "r"(b[0]), "r"(b[1]));
}
#define LDSM_X4(r0, r1, r2, r3, a)                                               \
    asm volatile("ldmatrix.sync.aligned.m8n8.x4.shared.b16 {%0,%1,%2,%3}, [%4];" \
                 : "=r"(r0), "=r"(r1), "=r"(r2), "=r"(r3) : "r"(a))
#define LDSM_X4_T(r0, r1, r2, r3, a)                                                   \
    asm volatile("ldmatrix.sync.aligned.m8n8.x4.trans.shared.b16 {%0,%1,%2,%3}, [%4];" \
                 : "=r"(r0), "=r"(r1), "=r"(r2), "=r"(r3) : "r"(a))
#define CP16(dst, src) \
    asm volatile("cp.async.cg.shared.global [%0], [%1], 16;" :: "r"(dst), "l"(src) : "memory")
#define CP_COMMIT() asm volatile("cp.async.commit_group;" ::: "memory")
#define CP_WAIT(n)  asm volatile("cp.async.wait_group %0;" :: "n"(n) : "memory")

// swizzled byte offset within a tile: row (key) 0..63, chunk (16B) 0..7
__device__ __forceinline__ uint32_t sw_off(int row, int chunk) {
    return (uint32_t)(row * 128 + ((chunk ^ (row & 7)) << 4));
}

// ---------------------------------------------------------------- fused pre-pass
__global__ void prepass(const float* __restrict__ k, const float* __restrict__ v,
                        const int* __restrict__ m) {
    if (blockIdx.x < MASK_BLOCKS) {
        const size_t i = (size_t)blockIdx.x * 256 + threadIdx.x;
        const int4 t = reinterpret_cast<const int4*>(m)[i];
        unsigned nib = (unsigned)(t.x != 0) | ((unsigned)(t.y != 0) << 1) |
                       ((unsigned)(t.z != 0) << 2) | ((unsigned)(t.w != 0) << 3);
        unsigned w = nib << ((threadIdx.x & 7) * 4);
        w |= __shfl_xor_sync(0xffffffffu, w, 1);
        w |= __shfl_xor_sync(0xffffffffu, w, 2);
        w |= __shfl_xor_sync(0xffffffffu, w, 4);
        if ((threadIdx.x & 7) == 0) g_mbits[i >> 3] = w;
    } else {
        const size_t i = ((size_t)(blockIdx.x - MASK_BLOCKS) * 256 + threadIdx.x) * 4;
        float4 tk = *reinterpret_cast<const float4*>(k + i);
        float4 tv = *reinterpret_cast<const float4*>(v + i);
        uint2 uk = make_uint2(packf16(tk.x, tk.y), packf16(tk.z, tk.w));
        uint2 uv = make_uint2(packf16(tv.x, tv.y), packf16(tv.z, tv.w));
        *reinterpret_cast<uint2*>(g_kh + i) = uk;
        *reinterpret_cast<uint2*>(g_vh + i) = uv;
    }
}

// ---------------------------------------------------------------- attention
__global__ __launch_bounds__(256, 2) void attn_mma(
    const float* __restrict__ Q, float* __restrict__ Out)
{
    extern __shared__ char smc[];
    const uint32_t smb = smem_u32(smc);

    const int tid  = threadIdx.x;
    const int lane = tid & 31;
    const int wid  = tid >> 5;
    const int gid  = lane >> 2;        // 0..7
    const int twoq = (lane & 3) * 2;   // 0,2,4,6
    const int mat  = lane >> 3, mr = lane & 7;

    const int bh = blockIdx.y;
    const int b  = bh >> 4;            // H == 16
    const int qbase = blockIdx.x * BM;
    const int qrow  = qbase + wid * 16 + gid;   // row0; row1 = qrow + 8

    const float*  qp = Q + (size_t)bh * S * Dh;
    const __half* kp = g_kh + (size_t)bh * S * Dh;
    const __half* vp = g_vh + (size_t)bh * S * Dh;

    // thread-constant swizzled LDSM offsets (key&7 == mr in both loops):
    //   MMA1 addr = Kb + kc[kt] + ntp*2048
    //   MMA2 addr = Vb + vc[ntp] + kt*2048
    uint32_t kc[4], vc[4];
    {
        const uint32_t kbase = (uint32_t)((((mat & 2) << 2) + mr) * 128);
        const uint32_t vbase = (uint32_t)((((mat & 1) << 3) + mr) * 128);
        #pragma unroll
        for (int i = 0; i < 4; ++i) {
            kc[i] = kbase + (uint32_t)((((2 * i + (mat & 1)) ^ mr) << 4));
            vc[i] = vbase + (uint32_t)((((2 * i + (mat >> 1)) ^ mr) << 4));
        }
    }

    // staging: 512 16B-chunks per tensor per tile; 2 per thread
    const int c0r = tid >> 3,         c0c = tid & 7;
    const int c1r = (tid + 256) >> 3, c1c = tid & 7;
    const uint32_t st_k0 = sw_off(c0r, c0c), st_k1 = sw_off(c1r, c1c);
    const int g0 = c0r * Dh + c0c * 8, g1 = c1r * Dh + c1c * 8;

    // ---- prologue: stage tiles 0 and 1
    #pragma unroll
    for (int pt = 0; pt < 2; ++pt) {
        const uint32_t ko = smb + pt * TILE_BYTES;
        const uint32_t vo = smb + VBASE + pt * TILE_BYTES;
        const __half* ks = kp + (size_t)pt * BN * Dh;
        const __half* vs = vp + (size_t)pt * BN * Dh;
        CP16(ko + st_k0, ks + g0);
        CP16(ko + st_k1, ks + g1);
        CP16(vo + st_k0, vs + g0);
        CP16(vo + st_k1, vs + g1);
        CP_COMMIT();
    }

    // ---- Q fragments (pre-scaled by 1/8*log2e), reused for all tiles
    uint32_t qa[4][4];
    {
        const float* q0 = qp + (size_t)qrow * Dh;
        const float* q8 = q0 + 8 * Dh;
        #pragma unroll
        for (int kt = 0; kt < 4; ++kt) {
            const int d0 = kt * 16 + twoq;
            float2 x0 = *(const float2*)(q0 + d0);
            float2 x8 = *(const float2*)(q8 + d0);
            float2 y0 = *(const float2*)(q0 + d0 + 8);
            float2 y8 = *(const float2*)(q8 + d0 + 8);
            qa[kt][0] = packf16(x0.x * QSCALE, x0.y * QSCALE);
            qa[kt][1] = packf16(x8.x * QSCALE, x8.y * QSCALE);
            qa[kt][2] = packf16(y0.x * QSCALE, y0.y * QSCALE);
            qa[kt][3] = packf16(y8.x * QSCALE, y8.y * QSCALE);
        }
    }

    float of[8][4];
    #pragma unroll
    for (int nt = 0; nt < 8; ++nt)
        #pragma unroll
        for (int j = 0; j < 4; ++j) of[nt][j] = 0.f;
    float l0 = 0.f, l1 = 0.f;

    const unsigned* mrow = g_mbits + ((size_t)(b * S) + qrow) * (S / 32);

    int bi = 0;    // buffer of tile t
    int si = 2;    // buffer of tile t+2 (staging target)
    for (int t = 0; t < TILES; ++t) {
        if (t + 1 < TILES) { CP_WAIT(1); } else { CP_WAIT(0); }
        uint2 mwa = *(const uint2*)(mrow + t * 2);
        uint2 mwb = *(const uint2*)(mrow + 8 * (S / 32) + t * 2);

        __syncthreads();   // tile t visible; buffer si fully drained

        // ---- stage tile t+2 into buffer si
        if (t + 2 < TILES) {
            const uint32_t ko = smb + si * TILE_BYTES;
            const uint32_t vo = smb + VBASE + si * TILE_BYTES;
            const __half* ks = kp + (size_t)(t + 2) * BN * Dh;
            const __half* vs = vp + (size_t)(t + 2) * BN * Dh;
            CP16(ko + st_k0, ks + g0);
            CP16(ko + st_k1, ks + g1);
            CP16(vo + st_k0, vs + g0);
            CP16(vo + st_k1, vs + g1);
            CP_COMMIT();
        }

        const uint32_t Kb = smb + bi * TILE_BYTES;
        const uint32_t Vb = smb + VBASE + bi * TILE_BYTES;

        // ---- MMA1: S2 = (Q*scale*log2e) K^T ; addr = (Kb+kc[kt]) + ntp*2048 (imm)
        float sf[8][4];
        #pragma unroll
        for (int nt = 0; nt < 8; ++nt)
            #pragma unroll
            for (int j = 0; j < 4; ++j) sf[nt][j] = 0.f;

        #pragma unroll
        for (int kt = 0; kt < 4; ++kt) {
            const uint32_t rk = Kb + kc[kt];
            #pragma unroll
            for (int ntp = 0; ntp < 4; ++ntp) {
                uint32_t b0, b1, b2, b3;
                LDSM_X4(b0, b1, b2, b3, rk + ntp * 2048);
                uint32_t f0[2] = { b0, b1 }, f1[2] = { b2, b3 };
                mma_f16(sf[2 * ntp],     qa[kt], f0);
                mma_f16(sf[2 * ntp + 1], qa[kt], f1);
            }
        }

        // ---- mask + 2^s (unnormalized softmax in base-2)
        #pragma unroll
        for (int nt = 0; nt < 8; ++nt) {
            const int sh = (nt & 3) * 8 + twoq;
            const unsigned wa = ((nt < 4) ? mwa.x : mwa.y) >> sh;
            const unsigned wb = ((nt < 4) ? mwb.x : mwb.y) >> sh;
            float e0 = (wa & 1u) ? ex2f(sf[nt][0]) : 0.f;
            float e1 = (wa & 2u) ? ex2f(sf[nt][1]) : 0.f;
            float e2 = (wb & 1u) ? ex2f(sf[nt][2]) : 0.f;
            float e3 = (wb & 2u) ? ex2f(sf[nt][3]) : 0.f;
            l0 += e0 + e1; l1 += e2 + e3;
            sf[nt][0] = e0; sf[nt][1] = e1; sf[nt][2] = e2; sf[nt][3] = e3;
        }

        // ---- P fragments: C layout maps onto A layout (pure cvt)
        uint32_t pa[4][4];
        #pragma unroll
        for (int kt = 0; kt < 4; ++kt) {
            pa[kt][0] = packf16(sf[2 * kt][0],     sf[2 * kt][1]);
            pa[kt][1] = packf16(sf[2 * kt][2],     sf[2 * kt][3]);
            pa[kt][2] = packf16(sf[2 * kt + 1][0], sf[2 * kt + 1][1]);
            pa[kt][3] = packf16(sf[2 * kt + 1][2], sf[2 * kt + 1][3]);
        }

        // ---- MMA2: O += P V ; addr = (Vb+vc[ntp]) + kt*2048 (imm)
        {
            uint32_t rv0 = Vb + vc[0], rv1 = Vb + vc[1], rv2 = Vb + vc[2], rv3 = Vb + vc[3];
            #pragma unroll
            for (int kt = 0; kt < 4; ++kt) {
                #pragma unroll
                for (int ntp = 0; ntp < 4; ++ntp) {
                    const uint32_t rv = (ntp == 0) ? rv0 : (ntp == 1) ? rv1 : (ntp == 2) ? rv2 : rv3;
                    uint32_t b0, b1, b2, b3;
                    LDSM_X4_T(b0, b1, b2, b3, rv + kt * 2048);
                    uint32_t f0[2] = { b0, b1 }, f1[2] = { b2, b3 };
                    mma_f16(of[2 * ntp],     pa[kt], f0);
                    mma_f16(of[2 * ntp + 1], pa[kt], f1);
                }
            }
        }

        bi = (bi == 2) ? 0 : bi + 1;
        si = (si == 2) ? 0 : si + 1;
    }

    // ---- epilogue: normalize and store
    l0 += __shfl_xor_sync(0xffffffffu, l0, 1);
    l0 += __shfl_xor_sync(0xffffffffu, l0, 2);
    l1 += __shfl_xor_sync(0xffffffffu, l1, 1);
    l1 += __shfl_xor_sync(0xffffffffu, l1, 2);
    const float inv0 = 1.0f / l0, inv1 = 1.0f / l1;

    float* o0 = Out + ((size_t)bh * S + qrow) * Dh;
    float* o8 = o0 + 8 * Dh;
    #pragma unroll
    for (int nt = 0; nt < 8; ++nt) {
        const int d = nt * 8 + twoq;
        *(float2*)(o0 + d) = make_float2(of[nt][0] * inv0, of[nt][1] * inv0);
        *(float2*)(o8 + d) = make_float2(of[nt][2] * inv1, of[nt][3] * inv1);
    }
}

// ---------------------------------------------------------------- launch
extern "C" void kernel_launch(void* const* d_in, const int* in_sizes, int n_in,
                              void* d_out, int out_size)
{
    const float* q    = (const float*)d_in[0];
    const float* k    = (const float*)d_in[1];
    const float* v    = (const float*)d_in[2];
    const int*   mask = (const int*)d_in[3];
    float* out = (float*)d_out;

    prepass<<<MASK_BLOCKS + CVT_BLOCKS, 256>>>(k, v, mask);

    cudaFuncSetAttribute(attn_mma, cudaFuncAttributeMaxDynamicSharedMemorySize, SMEM_BYTES);
    dim3 grid(S / BM, B * H);   // 16 x 64 = 1024 CTAs
    attn_mma<<<grid, 256, SMEM_BYTES>>>(q, out);
}

// round 14
// speedup vs baseline: 1.2507x; 1.0407x over previous
#include <cuda_runtime.h>
#include <cuda_fp16.h>
#include <cstdint>
#include <math.h>

// ---------------------------------------------------------------- problem
namespace {
constexpr int B = 4, H = 16, S = 2048, Dh = 64;
constexpr int BM = 128;          // query rows per CTA (8 warps x 16 rows)
constexpr int BN = 64;           // keys per tile
constexpr int TILES = S / BN;    // 32
constexpr float QSCALE = 0.125f * 1.44269504089f;  // 1/sqrt(64) * log2(e) folded into Q
constexpr size_t NELEM = (size_t)B * H * S * Dh;   // 8.39M

// smem (bytes): half tiles 64 rows x 128B, XOR-swizzled, TRIPLE buffered
constexpr int TILE_BYTES = 8192;
constexpr int VBASE = 3 * TILE_BYTES;      // 24576
constexpr int SMEM_BYTES = 6 * TILE_BYTES; // 49152

// prepass block ranges
constexpr int MASKB_BLOCKS = (B * S * 64) / 256;     // 2048  (1 thread = 32 mask elems)
constexpr int CVT_BLOCKS   = (int)(NELEM / 4 / 256); // 8192
}

// scratch: permuted byte-mask + fp16 K/V
// mask byte layout per row: offset = (col%8/2)*512 + (col/8)*2 + (col&1); value 0xFF/0x00
__device__ unsigned char g_mbytes[(size_t)B * S * S];
__device__ __half g_kh[NELEM];
__device__ __half g_vh[NELEM];

// ---------------------------------------------------------------- helpers
__device__ __forceinline__ uint32_t smem_u32(const void* p) {
    uint32_t a;
    asm("{ .reg .u64 t; cvta.to.shared.u64 t, %1; cvt.u32.u64 %0, t; }" : "=r"(a) : "l"(p));
    return a;
}
__device__ __forceinline__ uint32_t packf16(float lo, float hi) {
    uint32_t d;
    asm("cvt.rn.f16x2.f32 %0, %1, %2;" : "=r"(d) : "f"(hi), "f"(lo));
    return d;
}
__device__ __forceinline__ uint32_t h2exp2(uint32_t x) {
    uint32_t y; asm("ex2.approx.f16x2 %0, %1;" : "=r"(y) : "r"(x)); return y;
}
__device__ __forceinline__ void mma_f16(float* c, const uint32_t* a, const uint32_t* b) {
    asm volatile(
        "mma.sync.aligned.m16n8k16.row.col.f32.f16.f16.f32 "
        "{%0,%1,%2,%3}, {%4,%5,%6,%7}, {%8,%9}, {%0,%1,%2,%3};"
        : "+f"(c[0]), "+f"(c[1]), "+f"(c[2]), "+f"(c[3])
        : "r"(a[0]), "r"(a[1]), "r"(a[2]), "r"(a[3]), "r"(b[0]), "r"(b[1]));
}
#define LDSM_X4(r0, r1, r2, r3, a)                                               \
    asm volatile("ldmatrix.sync.aligned.m8n8.x4.shared.b16 {%0,%1,%2,%3}, [%4];" \
                 : "=r"(r0), "=r"(r1), "=r"(r2), "=r"(r3) : "r"(a))
#define LDSM_X4_T(r0, r1, r2, r3, a)                                                   \
    asm volatile("ldmatrix.sync.aligned.m8n8.x4.trans.shared.b16 {%0,%1,%2,%3}, [%4];" \
                 : "=r"(r0), "=r"(r1), "=r"(r2), "=r"(r3) : "r"(a))
#define CP16(dst, src) \
    asm volatile("cp.async.cg.shared.global [%0], [%1], 16;" :: "r"(dst), "l"(src) : "memory")
#define CP_COMMIT() asm volatile("cp.async.commit_group;" ::: "memory")
#define CP_WAIT(n)  asm volatile("cp.async.wait_group %0;" :: "n"(n) : "memory")

// swizzled byte offset within a K/V tile: row 0..63, chunk (16B) 0..7
__device__ __forceinline__ uint32_t sw_off(int row, int chunk) {
    return (uint32_t)(row * 128 + ((chunk ^ (row & 7)) << 4));
}

// ---------------------------------------------------------------- fused pre-pass
// blocks [0, MASKB_BLOCKS): mask -> permuted bytes.  rest: K/V -> fp16.
__global__ void prepass(const float* __restrict__ k, const float* __restrict__ v,
                        const int* __restrict__ m) {
    if (blockIdx.x < MASKB_BLOCKS) {
        const unsigned gid = blockIdx.x * 256 + threadIdx.x;   // < B*S*64
        const int r  = gid >> 6;        // row in [0, B*S)
        const int kb = gid & 63;        // 32-key block
        const int4* src = reinterpret_cast<const int4*>(m) + ((size_t)r * S + kb * 32) / 4;
        unsigned by[32];
        #pragma unroll
        for (int i = 0; i < 8; ++i) {
            int4 t = src[i];
            by[4 * i + 0] = (t.x != 0) ? 0xFFu : 0u;
            by[4 * i + 1] = (t.y != 0) ? 0xFFu : 0u;
            by[4 * i + 2] = (t.z != 0) ? 0xFFu : 0u;
            by[4 * i + 3] = (t.w != 0) ? 0xFFu : 0u;
        }
        unsigned char* dst = g_mbytes + (size_t)r * S + kb * 8;
        #pragma unroll
        for (int q = 0; q < 4; ++q) {
            uint2 o;
            o.x = by[2*q]      | (by[2*q+1] << 8)  | (by[8+2*q] << 16)  | (by[8+2*q+1] << 24);
            o.y = by[16+2*q]   | (by[16+2*q+1]<<8) | (by[24+2*q] << 16) | (by[24+2*q+1] << 24);
            *reinterpret_cast<uint2*>(dst + q * 512) = o;
        }
    } else {
        const size_t i = ((size_t)(blockIdx.x - MASKB_BLOCKS) * 256 + threadIdx.x) * 4;
        float4 tk = *reinterpret_cast<const float4*>(k + i);
        float4 tv = *reinterpret_cast<const float4*>(v + i);
        uint2 uk = make_uint2(packf16(tk.x, tk.y), packf16(tk.z, tk.w));
        uint2 uv = make_uint2(packf16(tv.x, tv.y), packf16(tv.z, tv.w));
        *reinterpret_cast<uint2*>(g_kh + i) = uk;
        *reinterpret_cast<uint2*>(g_vh + i) = uv;
    }
}

// ---------------------------------------------------------------- attention
__global__ __launch_bounds__(256, 2) void attn_mma(
    const float* __restrict__ Q, float* __restrict__ Out)
{
    extern __shared__ char smc[];
    const uint32_t smb = smem_u32(smc);

    const int tid  = threadIdx.x;
    const int lane = tid & 31;
    const int wid  = tid >> 5;
    const int gid  = lane >> 2;        // 0..7
    const int twoq = (lane & 3) * 2;   // 0,2,4,6
    const int mat  = lane >> 3, mr = lane & 7;

    const int bh = blockIdx.y;
    const int b  = bh >> 4;            // H == 16
    const int qbase = blockIdx.x * BM;
    const int qrow  = qbase + wid * 16 + gid;   // row0; row1 = qrow + 8

    const float*  qp = Q + (size_t)bh * S * Dh;
    const __half* kp = g_kh + (size_t)bh * S * Dh;
    const __half* vp = g_vh + (size_t)bh * S * Dh;

    // permuted mask-byte pointers (one uint4 per row-block per tile)
    const unsigned char* mbA = g_mbytes + ((size_t)(b * S) + qrow) * S + (lane & 3) * 512;
    const unsigned char* mbB = mbA + 8 * S;

    // thread-constant swizzled LDSM offsets (key&7 == mr in both loops)
    uint32_t kc[4], vc[4];
    {
        const uint32_t kbase = (uint32_t)((((mat & 2) << 2) + mr) * 128);
        const uint32_t vbase = (uint32_t)((((mat & 1) << 3) + mr) * 128);
        #pragma unroll
        for (int i = 0; i < 4; ++i) {
            kc[i] = kbase + (uint32_t)((((2 * i + (mat & 1)) ^ mr) << 4));
            vc[i] = vbase + (uint32_t)((((2 * i + (mat >> 1)) ^ mr) << 4));
        }
    }

    // staging: 512 16B-chunks per tensor per tile; 2 per thread
    const int c0r = tid >> 3,         c0c = tid & 7;
    const int c1r = (tid + 256) >> 3, c1c = tid & 7;
    const uint32_t st_k0 = sw_off(c0r, c0c), st_k1 = sw_off(c1r, c1c);
    const int g0 = c0r * Dh + c0c * 8, g1 = c1r * Dh + c1c * 8;

    // ---- prologue: stage tiles 0 and 1
    #pragma unroll
    for (int pt = 0; pt < 2; ++pt) {
        const uint32_t ko = smb + pt * TILE_BYTES;
        const uint32_t vo = smb + VBASE + pt * TILE_BYTES;
        const __half* ks = kp + (size_t)pt * BN * Dh;
        const __half* vs = vp + (size_t)pt * BN * Dh;
        CP16(ko + st_k0, ks + g0);
        CP16(ko + st_k1, ks + g1);
        CP16(vo + st_k0, vs + g0);
        CP16(vo + st_k1, vs + g1);
        CP_COMMIT();
    }

    // ---- Q fragments (pre-scaled by 1/8*log2e), reused for all tiles
    uint32_t qa[4][4];
    {
        const float* q0 = qp + (size_t)qrow * Dh;
        const float* q8 = q0 + 8 * Dh;
        #pragma unroll
        for (int kt = 0; kt < 4; ++kt) {
            const int d0 = kt * 16 + twoq;
            float2 x0 = *(const float2*)(q0 + d0);
            float2 x8 = *(const float2*)(q8 + d0);
            float2 y0 = *(const float2*)(q0 + d0 + 8);
            float2 y8 = *(const float2*)(q8 + d0 + 8);
            qa[kt][0] = packf16(x0.x * QSCALE, x0.y * QSCALE);
            qa[kt][1] = packf16(x8.x * QSCALE, x8.y * QSCALE);
            qa[kt][2] = packf16(y0.x * QSCALE, y0.y * QSCALE);
            qa[kt][3] = packf16(y8.x * QSCALE, y8.y * QSCALE);
        }
    }

    float of[8][4];
    #pragma unroll
    for (int nt = 0; nt < 8; ++nt)
        #pragma unroll
        for (int j = 0; j < 4; ++j) of[nt][j] = 0.f;
    float lacc[4] = { 0.f, 0.f, 0.f, 0.f };   // row sums via ones-MMA (f32)
    const uint32_t onesb[2] = { 0x3C003C00u, 0x3C003C00u };

    int bi = 0;    // buffer of tile t
    int si = 2;    // buffer of tile t+2 (staging target)
    for (int t = 0; t < TILES; ++t) {
        if (t + 1 < TILES) { CP_WAIT(1); } else { CP_WAIT(0); }
        // mask bytes for this tile (independent global loads, issue early)
        const uint4 MA = *reinterpret_cast<const uint4*>(mbA + t * 16);
        const uint4 MB = *reinterpret_cast<const uint4*>(mbB + t * 16);

        __syncthreads();   // tile t visible; buffer si fully drained

        // ---- stage tile t+2 into buffer si
        if (t + 2 < TILES) {
            const uint32_t ko = smb + si * TILE_BYTES;
            const uint32_t vo = smb + VBASE + si * TILE_BYTES;
            const __half* ks = kp + (size_t)(t + 2) * BN * Dh;
            const __half* vs = vp + (size_t)(t + 2) * BN * Dh;
            CP16(ko + st_k0, ks + g0);
            CP16(ko + st_k1, ks + g1);
            CP16(vo + st_k0, vs + g0);
            CP16(vo + st_k1, vs + g1);
            CP_COMMIT();
        }

        const uint32_t Kb = smb + bi * TILE_BYTES;
        const uint32_t Vb = smb + VBASE + bi * TILE_BYTES;

        // ---- MMA1: S2 = (Q*scale*log2e) K^T
        float sf[8][4];
        #pragma unroll
        for (int nt = 0; nt < 8; ++nt)
            #pragma unroll
            for (int j = 0; j < 4; ++j) sf[nt][j] = 0.f;

        #pragma unroll
        for (int kt = 0; kt < 4; ++kt) {
            const uint32_t rk = Kb + kc[kt];
            #pragma unroll
            for (int ntp = 0; ntp < 4; ++ntp) {
                uint32_t b0, b1, b2, b3;
                LDSM_X4(b0, b1, b2, b3, rk + ntp * 2048);
                uint32_t f0[2] = { b0, b1 }, f1[2] = { b2, b3 };
                mma_f16(sf[2 * ntp],     qa[kt], f0);
                mma_f16(sf[2 * ntp + 1], qa[kt], f1);
            }
        }

        // ---- pack -> 2^s (f16x2 MUFU) -> byte-mask AND ; l via ones-MMA
        uint32_t pa[4][4];
        #pragma unroll
        for (int kt = 0; kt < 4; ++kt) {
            const uint32_t rA = (&MA.x)[kt], rB = (&MB.x)[kt];
            uint32_t p0 = packf16(sf[2 * kt][0],     sf[2 * kt][1]);
            uint32_t p1 = packf16(sf[2 * kt][2],     sf[2 * kt][3]);
            uint32_t p2 = packf16(sf[2 * kt + 1][0], sf[2 * kt + 1][1]);
            uint32_t p3 = packf16(sf[2 * kt + 1][2], sf[2 * kt + 1][3]);
            p0 = h2exp2(p0) & __byte_perm(rA, 0u, 0x1100);
            p1 = h2exp2(p1) & __byte_perm(rB, 0u, 0x1100);
            p2 = h2exp2(p2) & __byte_perm(rA, 0u, 0x3322);
            p3 = h2exp2(p3) & __byte_perm(rB, 0u, 0x3322);
            pa[kt][0] = p0; pa[kt][1] = p1; pa[kt][2] = p2; pa[kt][3] = p3;
            mma_f16(lacc, pa[kt], onesb);   // row sums, exact f32, same P as numerator
        }

        // ---- MMA2: O += P V
        {
            uint32_t rv0 = Vb + vc[0], rv1 = Vb + vc[1], rv2 = Vb + vc[2], rv3 = Vb + vc[3];
            #pragma unroll
            for (int kt = 0; kt < 4; ++kt) {
                #pragma unroll
                for (int ntp = 0; ntp < 4; ++ntp) {
                    const uint32_t rv = (ntp == 0) ? rv0 : (ntp == 1) ? rv1 : (ntp == 2) ? rv2 : rv3;
                    uint32_t b0, b1, b2, b3;
                    LDSM_X4_T(b0, b1, b2, b3, rv + kt * 2048);
                    uint32_t f0[2] = { b0, b1 }, f1[2] = { b2, b3 };
                    mma_f16(of[2 * ntp],     pa[kt], f0);
                    mma_f16(of[2 * ntp + 1], pa[kt], f1);
                }
            }
        }

        bi = (bi == 2) ? 0 : bi + 1;
        si = (si == 2) ? 0 : si + 1;
    }

    // ---- epilogue: normalize and store (lacc cols all equal -> no shuffles)
    const float inv0 = 1.0f / lacc[0], inv1 = 1.0f / lacc[2];

    float* o0 = Out + ((size_t)bh * S + qrow) * Dh;
    float* o8 = o0 + 8 * Dh;
    #pragma unroll
    for (int nt = 0; nt < 8; ++nt) {
        const int d = nt * 8 + twoq;
        *(float2*)(o0 + d) = make_float2(of[nt][0] * inv0, of[nt][1] * inv0);
        *(float2*)(o8 + d) = make_float2(of[nt][2] * inv1, of[nt][3] * inv1);
    }
}

// ---------------------------------------------------------------- launch
extern "C" void kernel_launch(void* const* d_in, const int* in_sizes, int n_in,
                              void* d_out, int out_size)
{
    const float* q    = (const float*)d_in[0];
    const float* k    = (const float*)d_in[1];
    const float* v    = (const float*)d_in[2];
    const int*   mask = (const int*)d_in[3];
    float* out = (float*)d_out;

    prepass<<<MASKB_BLOCKS + CVT_BLOCKS, 256>>>(k, v, mask);

    cudaFuncSetAttribute(attn_mma, cudaFuncAttributeMaxDynamicSharedMemorySize, SMEM_BYTES);
    dim3 grid(S / BM, B * H);   // 16 x 64 = 1024 CTAs
    attn_mma<<<grid, 256, SMEM_BYTES>>>(q, out);
}

// round 15
// speedup vs baseline: 1.2520x; 1.0010x over previous
#include <cuda_runtime.h>
#include <cuda_fp16.h>
#include <cstdint>
#include <math.h>

// ---------------------------------------------------------------- problem
namespace {
constexpr int B = 4, H = 16, S = 2048, Dh = 64;
constexpr int BM = 128;          // query rows per CTA (8 warps x 16 rows)
constexpr int BN = 64;           // keys per tile
constexpr int TILES = S / BN;    // 32
constexpr float QSCALE = 0.125f * 1.44269504089f;  // 1/sqrt(64) * log2(e) folded into Q
constexpr size_t NELEM = (size_t)B * H * S * Dh;   // 8.39M

// smem (bytes): half tiles 64 rows x 128B, XOR-swizzled, TRIPLE buffered
constexpr int TILE_BYTES = 8192;
constexpr int VBASE = 3 * TILE_BYTES;      // 24576
constexpr int SMEM_BYTES = 6 * TILE_BYTES; // 49152

// prepass block ranges
constexpr int MASKB_BLOCKS = (B * S * 64) / 256;     // 2048
constexpr int CVT_BLOCKS   = (int)(NELEM / 4 / 256); // 8192
}

// scratch: permuted byte-mask + fp16 K/V
// mask byte layout per row: offset = (col%8/2)*512 + (col/8)*2 + (col&1); value 0xFF/0x00
__device__ unsigned char g_mbytes[(size_t)B * S * S];
__device__ __half g_kh[NELEM];
__device__ __half g_vh[NELEM];

// ---------------------------------------------------------------- helpers
__device__ __forceinline__ uint32_t smem_u32(const void* p) {
    uint32_t a;
    asm("{ .reg .u64 t; cvta.to.shared.u64 t, %1; cvt.u32.u64 %0, t; }" : "=r"(a) : "l"(p));
    return a;
}
__device__ __forceinline__ uint32_t packf16(float lo, float hi) {
    uint32_t d;
    asm("cvt.rn.f16x2.f32 %0, %1, %2;" : "=r"(d) : "f"(hi), "f"(lo));
    return d;
}
__device__ __forceinline__ uint32_t h2exp2(uint32_t x) {
    uint32_t y; asm("ex2.approx.f16x2 %0, %1;" : "=r"(y) : "r"(x)); return y;
}
__device__ __forceinline__ void mma_f16(float* c, const uint32_t* a, const uint32_t* b) {
    asm volatile(
        "mma.sync.aligned.m16n8k16.row.col.f32.f16.f16.f32 "
        "{%0,%1,%2,%3}, {%4,%5,%6,%7}, {%8,%9}, {%0,%1,%2,%3};"
        : "+f"(c[0]), "+f"(c[1]), "+f"(c[2]), "+f"(c[3])
        : "r"(a[0]), "r"(a[1]), "r"(a[2]), "r"(a[3]), "r"(b[0]), "r"(b[1]));
}
#define LDSM_X4(r0, r1, r2, r3, a)                                               \
    asm volatile("ldmatrix.sync.aligned.m8n8.x4.shared.b16 {%0,%1,%2,%3}, [%4];" \
                 : "=r"(r0), "=r"(r1), "=r"(r2), "=r"(r3) : "r"(a))
#define LDSM_X4_T(r0, r1, r2, r3, a)                                                   \
    asm volatile("ldmatrix.sync.aligned.m8n8.x4.trans.shared.b16 {%0,%1,%2,%3}, [%4];" \
                 : "=r"(r0), "=r"(r1), "=r"(r2), "=r"(r3) : "r"(a))
#define CP16(dst, src) \
    asm volatile("cp.async.cg.shared.global [%0], [%1], 16;" :: "r"(dst), "l"(src) : "memory")
#define CP_COMMIT() asm volatile("cp.async.commit_group;" ::: "memory")
#define CP_WAIT(n)  asm volatile("cp.async.wait_group %0;" :: "n"(n) : "memory")

// swizzled byte offset within a K/V tile: row 0..63, chunk (16B) 0..7
__device__ __forceinline__ uint32_t sw_off(int row, int chunk) {
    return (uint32_t)(row * 128 + ((chunk ^ (row & 7)) << 4));
}

// ---------------------------------------------------------------- fused pre-pass
__global__ void prepass(const float* __restrict__ k, const float* __restrict__ v,
                        const int* __restrict__ m) {
    if (blockIdx.x < MASKB_BLOCKS) {
        const unsigned gid = blockIdx.x * 256 + threadIdx.x;   // < B*S*64
        const int r  = gid >> 6;        // row in [0, B*S)
        const int kb = gid & 63;        // 32-key block
        const int4* src = reinterpret_cast<const int4*>(m) + ((size_t)r * S + kb * 32) / 4;
        unsigned by[32];
        #pragma unroll
        for (int i = 0; i < 8; ++i) {
            int4 t = src[i];
            by[4 * i + 0] = (t.x != 0) ? 0xFFu : 0u;
            by[4 * i + 1] = (t.y != 0) ? 0xFFu : 0u;
            by[4 * i + 2] = (t.z != 0) ? 0xFFu : 0u;
            by[4 * i + 3] = (t.w != 0) ? 0xFFu : 0u;
        }
        unsigned char* dst = g_mbytes + (size_t)r * S + kb * 8;
        #pragma unroll
        for (int q = 0; q < 4; ++q) {
            uint2 o;
            o.x = by[2*q]      | (by[2*q+1] << 8)  | (by[8+2*q] << 16)  | (by[8+2*q+1] << 24);
            o.y = by[16+2*q]   | (by[16+2*q+1]<<8) | (by[24+2*q] << 16) | (by[24+2*q+1] << 24);
            *reinterpret_cast<uint2*>(dst + q * 512) = o;
        }
    } else {
        const size_t i = ((size_t)(blockIdx.x - MASKB_BLOCKS) * 256 + threadIdx.x) * 4;
        float4 tk = *reinterpret_cast<const float4*>(k + i);
        float4 tv = *reinterpret_cast<const float4*>(v + i);
        uint2 uk = make_uint2(packf16(tk.x, tk.y), packf16(tk.z, tk.w));
        uint2 uv = make_uint2(packf16(tv.x, tv.y), packf16(tv.z, tv.w));
        *reinterpret_cast<uint2*>(g_kh + i) = uk;
        *reinterpret_cast<uint2*>(g_vh + i) = uv;
    }
}

// ---------------------------------------------------------------- attention
__global__ __launch_bounds__(256, 2) void attn_mma(
    const float* __restrict__ Q, float* __restrict__ Out)
{
    extern __shared__ char smc[];
    const uint32_t smb = smem_u32(smc);

    const int tid  = threadIdx.x;
    const int lane = tid & 31;
    const int wid  = tid >> 5;
    const int gid  = lane >> 2;        // 0..7
    const int twoq = (lane & 3) * 2;   // 0,2,4,6
    const int mat  = lane >> 3, mr = lane & 7;

    const int bh = blockIdx.y;
    const int b  = bh >> 4;            // H == 16
    const int qbase = blockIdx.x * BM;
    const int qrow  = qbase + wid * 16 + gid;   // row0; row1 = qrow + 8

    const float*  qp = Q + (size_t)bh * S * Dh;
    const __half* kp = g_kh + (size_t)bh * S * Dh;
    const __half* vp = g_vh + (size_t)bh * S * Dh;

    // permuted mask-byte pointers (one uint4 per row-block per tile)
    const unsigned char* mbA = g_mbytes + ((size_t)(b * S) + qrow) * S + (lane & 3) * 512;
    const unsigned char* mbB = mbA + 8 * S;

    // thread-constant swizzled LDSM offsets (key&7 == mr in both loops)
    uint32_t kc[4], vc[4];
    {
        const uint32_t kbase = (uint32_t)((((mat & 2) << 2) + mr) * 128);
        const uint32_t vbase = (uint32_t)((((mat & 1) << 3) + mr) * 128);
        #pragma unroll
        for (int i = 0; i < 4; ++i) {
            kc[i] = kbase + (uint32_t)((((2 * i + (mat & 1)) ^ mr) << 4));
            vc[i] = vbase + (uint32_t)((((2 * i + (mat >> 1)) ^ mr) << 4));
        }
    }

    // staging: 512 16B-chunks per tensor per tile; 2 per thread
    const int c0r = tid >> 3,         c0c = tid & 7;
    const int c1r = (tid + 256) >> 3, c1c = tid & 7;
    const uint32_t st_k0 = sw_off(c0r, c0c), st_k1 = sw_off(c1r, c1c);
    const int g0 = c0r * Dh + c0c * 8, g1 = c1r * Dh + c1c * 8;

    // ---- prologue: stage tiles 0 and 1
    #pragma unroll
    for (int pt = 0; pt < 2; ++pt) {
        const uint32_t ko = smb + pt * TILE_BYTES;
        const uint32_t vo = smb + VBASE + pt * TILE_BYTES;
        const __half* ks = kp + (size_t)pt * BN * Dh;
        const __half* vs = vp + (size_t)pt * BN * Dh;
        CP16(ko + st_k0, ks + g0);
        CP16(ko + st_k1, ks + g1);
        CP16(vo + st_k0, vs + g0);
        CP16(vo + st_k1, vs + g1);
        CP_COMMIT();
    }

    // ---- Q fragments (pre-scaled by 1/8*log2e), reused for all tiles
    uint32_t qa[4][4];
    {
        const float* q0 = qp + (size_t)qrow * Dh;
        const float* q8 = q0 + 8 * Dh;
        #pragma unroll
        for (int kt = 0; kt < 4; ++kt) {
            const int d0 = kt * 16 + twoq;
            float2 x0 = *(const float2*)(q0 + d0);
            float2 x8 = *(const float2*)(q8 + d0);
            float2 y0 = *(const float2*)(q0 + d0 + 8);
            float2 y8 = *(const float2*)(q8 + d0 + 8);
            qa[kt][0] = packf16(x0.x * QSCALE, x0.y * QSCALE);
            qa[kt][1] = packf16(x8.x * QSCALE, x8.y * QSCALE);
            qa[kt][2] = packf16(y0.x * QSCALE, y0.y * QSCALE);
            qa[kt][3] = packf16(y8.x * QSCALE, y8.y * QSCALE);
        }
    }

    float of[8][4];
    #pragma unroll
    for (int nt = 0; nt < 8; ++nt)
        #pragma unroll
        for (int j = 0; j < 4; ++j) of[nt][j] = 0.f;
    float lacc[4] = { 0.f, 0.f, 0.f, 0.f };   // row sums via ones-MMA (f32)
    const uint32_t onesb[2] = { 0x3C003C00u, 0x3C003C00u };

    int bi = 0;    // buffer of tile t
    int si = 2;    // buffer of tile t+2 (staging target)
    for (int t = 0; t < TILES; ++t) {
        if (t + 1 < TILES) { CP_WAIT(1); } else { CP_WAIT(0); }
        // mask bytes for this tile (independent global loads)
        const uint4 MA = *reinterpret_cast<const uint4*>(mbA + t * 16);
        const uint4 MB = *reinterpret_cast<const uint4*>(mbB + t * 16);

        __syncthreads();   // tile t visible; buffer si fully drained

        // ---- stage tile t+2 into buffer si
        if (t + 2 < TILES) {
            const uint32_t ko = smb + si * TILE_BYTES;
            const uint32_t vo = smb + VBASE + si * TILE_BYTES;
            const __half* ks = kp + (size_t)(t + 2) * BN * Dh;
            const __half* vs = vp + (size_t)(t + 2) * BN * Dh;
            CP16(ko + st_k0, ks + g0);
            CP16(ko + st_k1, ks + g1);
            CP16(vo + st_k0, vs + g0);
            CP16(vo + st_k1, vs + g1);
            CP_COMMIT();
        }

        const uint32_t Kb = smb + bi * TILE_BYTES;
        const uint32_t Vb = smb + VBASE + bi * TILE_BYTES;

        // ---- interleaved per 16-key group: MMA1 -> exp/mask -> l -> MMA2
        #pragma unroll
        for (int g = 0; g < 4; ++g) {
            // MMA1 for key group g (keys g*16 .. g*16+15)
            float s0[4] = {0.f, 0.f, 0.f, 0.f};
            float s1[4] = {0.f, 0.f, 0.f, 0.f};
            #pragma unroll
            for (int kt = 0; kt < 4; ++kt) {
                uint32_t b0, b1, b2, b3;
                LDSM_X4(b0, b1, b2, b3, Kb + kc[kt] + g * 2048);
                uint32_t f0[2] = { b0, b1 }, f1[2] = { b2, b3 };
                mma_f16(s0, qa[kt], f0);
                mma_f16(s1, qa[kt], f1);
            }

            // pack -> 2^s -> byte-mask AND
            const uint32_t rA = (&MA.x)[g], rB = (&MB.x)[g];
            uint32_t pg[4];
            pg[0] = h2exp2(packf16(s0[0], s0[1])) & __byte_perm(rA, 0u, 0x1100);
            pg[1] = h2exp2(packf16(s0[2], s0[3])) & __byte_perm(rB, 0u, 0x1100);
            pg[2] = h2exp2(packf16(s1[0], s1[1])) & __byte_perm(rA, 0u, 0x3322);
            pg[3] = h2exp2(packf16(s1[2], s1[3])) & __byte_perm(rB, 0u, 0x3322);

            // l row-sums (same P as numerator, exact f32)
            mma_f16(lacc, pg, onesb);

            // MMA2: O += P[:, g*16..] V[g*16.., :]
            #pragma unroll
            for (int dt = 0; dt < 4; ++dt) {
                uint32_t b0, b1, b2, b3;
                LDSM_X4_T(b0, b1, b2, b3, Vb + vc[dt] + g * 2048);
                uint32_t f0[2] = { b0, b1 }, f1[2] = { b2, b3 };
                mma_f16(of[2 * dt],     pg, f0);
                mma_f16(of[2 * dt + 1], pg, f1);
            }
        }

        bi = (bi == 2) ? 0 : bi + 1;
        si = (si == 2) ? 0 : si + 1;
    }

    // ---- epilogue: normalize and store (lacc cols equal within row -> no shuffles)
    const float inv0 = 1.0f / lacc[0], inv1 = 1.0f / lacc[2];

    float* o0 = Out + ((size_t)bh * S + qrow) * Dh;
    float* o8 = o0 + 8 * Dh;
    #pragma unroll
    for (int nt = 0; nt < 8; ++nt) {
        const int d = nt * 8 + twoq;
        *(float2*)(o0 + d) = make_float2(of[nt][0] * inv0, of[nt][1] * inv0);
        *(float2*)(o8 + d) = make_float2(of[nt][2] * inv1, of[nt][3] * inv1);
    }
}

// ---------------------------------------------------------------- launch
extern "C" void kernel_launch(void* const* d_in, const int* in_sizes, int n_in,
                              void* d_out, int out_size)
{
    const float* q    = (const float*)d_in[0];
    const float* k    = (const float*)d_in[1];
    const float* v    = (const float*)d_in[2];
    const int*   mask = (const int*)d_in[3];
    float* out = (float*)d_out;

    prepass<<<MASKB_BLOCKS + CVT_BLOCKS, 256>>>(k, v, mask);

    cudaFuncSetAttribute(attn_mma, cudaFuncAttributeMaxDynamicSharedMemorySize, SMEM_BYTES);
    dim3 grid(S / BM, B * H);   // 16 x 64 = 1024 CTAs
    attn_mma<<<grid, 256, SMEM_BYTES>>>(q, out);
}